// round 15
// baseline (speedup 1.0000x reference)
#include <cuda_runtime.h>
#include <cuda_bf16.h>

#define HID 512
#define BT  16
#define TT  2048
#define ISZ 32
#define NBLK 128
#define NTH  512
#define YSZ (BT*TT*ISZ)

// ---- shared memory word (u32) layout ---------------------------------------
#define OA0   0                 // L0 A: hi 16x256 | lo 16x256 (w_hh0), swizzled
#define OA1   8192              // L1 A: hi 16x512 | lo 16x512 (w_ih1|w_hh1)
#define OB    24576             // B: hi [L(2)][b(16)][256] | lo same (TMA-mc landed)
#define ORED  40960             // 16 warps x 256 floats
#define OBIAS 45056             // 32 floats
#define OWOUT 45088             // w_out row oc: 512 floats
#define OMBAR (OWOUT + 512)     // u64 mbarrier (word offset; *4 is 8B aligned)
#define SMEM_MAIN ((OMBAR + 2) * 4)

// ---- device scratch ---------------------------------------------------------
__device__ __align__(16) unsigned g_hp[2][16384];   // packed split-bf16 h (64KB/buf)
__device__ float g_gx0[(size_t)TT*NBLK*256];        // precomputed x@w_ih0^T
__device__ unsigned g_bar_count, g_bar_gen;

// ---- helpers ----------------------------------------------------------------
__device__ __forceinline__ void split2(float f0, float f1, unsigned &hi, unsigned &lo) {
    unsigned h;
    asm("cvt.rn.bf16x2.f32 %0, %1, %2;" : "=r"(h) : "f"(f1), "f"(f0));
    float r0 = f0 - __uint_as_float(h << 16);
    float r1 = f1 - __uint_as_float(h & 0xFFFF0000u);
    unsigned l;
    asm("cvt.rn.bf16x2.f32 %0, %1, %2;" : "=r"(l) : "f"(r1), "f"(r0));
    hi = h; lo = l;
}

__device__ __forceinline__ void mma_bf16(float* c, const unsigned* a, const unsigned* b) {
    asm volatile(
        "mma.sync.aligned.m16n8k16.row.col.f32.bf16.bf16.f32 "
        "{%0,%1,%2,%3}, {%4,%5,%6,%7}, {%8,%9}, {%0,%1,%2,%3};"
        : "+f"(c[0]), "+f"(c[1]), "+f"(c[2]), "+f"(c[3])
        : "r"(a[0]), "r"(a[1]), "r"(a[2]), "r"(a[3]), "r"(b[0]), "r"(b[1]));
}

__device__ __forceinline__ void ldsm4(unsigned &r0, unsigned &r1, unsigned &r2, unsigned &r3,
                                      unsigned addr) {
    asm volatile("ldmatrix.sync.aligned.m8n8.x4.shared.b16 {%0,%1,%2,%3}, [%4];"
                 : "=r"(r0), "=r"(r1), "=r"(r2), "=r"(r3) : "r"(addr));
}

__device__ __forceinline__ float sigf(float v) {
    return __fdividef(1.0f, 1.0f + __expf(-v));
}
__device__ __forceinline__ float tanh_fast(float v) {
    return __fdividef(2.0f, 1.0f + __expf(-2.0f * v)) - 1.0f;
}

__device__ __forceinline__ unsigned my_rank() {
    unsigned r; asm("mov.u32 %0, %%cluster_ctarank;" : "=r"(r)); return r;
}
__device__ __forceinline__ void mbar_init(unsigned mbar, unsigned cnt) {
    asm volatile("mbarrier.init.shared.b64 [%0], %1;" :: "r"(mbar), "r"(cnt) : "memory");
}
__device__ __forceinline__ void mbar_expect(unsigned mbar, unsigned bytes) {
    asm volatile("mbarrier.arrive.expect_tx.shared.b64 _, [%0], %1;"
                 :: "r"(mbar), "r"(bytes) : "memory");
}
__device__ __forceinline__ void mbar_wait(unsigned mbar, unsigned parity) {
    asm volatile(
        "{\n\t"
        ".reg .pred P;\n\t"
        "WL%=:\n\t"
        "mbarrier.try_wait.parity.acquire.cta.shared::cta.b64 P, [%0], %1, 0x989680;\n\t"
        "@!P bra WL%=;\n\t"
        "}"
        :: "r"(mbar), "r"(parity) : "memory");
}
__device__ __forceinline__ void bulk_mc(unsigned dst, const void* src, unsigned bytes,
                                        unsigned mbar, unsigned short mask) {
    asm volatile(
        "cp.async.bulk.shared::cluster.global.mbarrier::complete_tx::bytes.multicast::cluster "
        "[%0], [%1], %2, [%3], %4;"
        :: "r"(dst), "l"(src), "r"(bytes), "r"(mbar), "h"(mask) : "memory");
}

// THE PROVEN grid barrier (R12/R13): monotonic ticket, local target, store release.
__device__ __forceinline__ void grid_barrier(unsigned target) {
    __syncthreads();
    if (threadIdx.x == 0) {
        unsigned ticket = atomicAdd(&g_bar_count, 1u);
        if (ticket == target * NBLK - 1u) {
            __threadfence();
            *(volatile unsigned*)&g_bar_gen = target;
        } else {
            volatile unsigned* genp = &g_bar_gen;
            while (*genp < target) { }
        }
        asm volatile("fence.acq_rel.gpu;" ::: "memory");  // acquire for h reads
    }
    __syncthreads();
}

// ---- init -------------------------------------------------------------------
__global__ void init_zero_kernel() {
    int i = blockIdx.x * blockDim.x + threadIdx.x;
    if (i < 2 * 16384) (&g_hp[0][0])[i] = 0u;
    if (i == 0) { g_bar_count = 0u; g_bar_gen = 0u; }
}

// gx0[t][blk][g*4+u][b] = dot(x[b,t,:], w_ih0[g*512+blk*4+u, :])
__global__ void gx0_kernel(const float* __restrict__ x, const float* __restrict__ w_ih0) {
    __shared__ float sx[BT][ISZ];
    const int t = blockIdx.x;
    const int tid = threadIdx.x;
    for (int i = tid; i < BT * ISZ; i += 256) {
        int b = i >> 5, k = i & 31;
        sx[b][k] = x[((size_t)b * TT + t) * ISZ + k];
    }
    __syncthreads();
    const int grow = blockIdx.y * 256 + tid;   // 0..2047
    float4 w[8];
    #pragma unroll
    for (int i = 0; i < 8; i++)
        w[i] = *(const float4*)&w_ih0[grow * ISZ + i * 4];
    const int g = grow >> 9, ug = grow & 511;
    const int blk = ug >> 2, u = ug & 3;
    float* outp = &g_gx0[((size_t)t * NBLK + blk) * 256 + (g * 4 + u) * 16];
    #pragma unroll 4
    for (int b = 0; b < BT; b++) {
        float s = 0.0f;
        #pragma unroll
        for (int i = 0; i < 8; i++) {
            s += w[i].x * sx[b][i*4+0] + w[i].y * sx[b][i*4+1]
               + w[i].z * sx[b][i*4+2] + w[i].w * sx[b][i*4+3];
        }
        outp[b] = s;
    }
}

// ---- main persistent kernel (cluster 2, TMA-multicast staging) --------------
__global__ void __launch_bounds__(NTH, 1) __cluster_dims__(2, 1, 1)
lstm_kernel(
    const float* __restrict__ w_hh0,
    const float* __restrict__ b_ih0, const float* __restrict__ b_hh0,
    const float* __restrict__ w_ih1, const float* __restrict__ w_hh1,
    const float* __restrict__ b_ih1, const float* __restrict__ b_hh1,
    const float* __restrict__ w_out, const float* __restrict__ b_out,
    float* __restrict__ out)
{
    extern __shared__ unsigned smu[];
    float* red  = reinterpret_cast<float*>(&smu[ORED]);
    float* bias = reinterpret_cast<float*>(&smu[OBIAS]);
    float* sWo  = reinterpret_cast<float*>(&smu[OWOUT]);
    const int tid = threadIdx.x;
    const int bid = blockIdx.x;
    const int j0  = bid * 4;
    const unsigned sbase = (unsigned)__cvta_generic_to_shared(smu);
    const unsigned mbar  = sbase + OMBAR * 4u;
    const unsigned rank  = my_rank();

    // y role: block owns output channel oc for 4 batches
    const int oc = bid & 31;
    const float bo = __ldg(&b_out[oc]);

    // ---- one-time: split-bf16 weights into smem, XOR-swizzled ----
    for (int i = tid; i < 16 * 256; i += NTH) {
        int r = i >> 8, w = i & 255;
        int grow = (r >> 2) * HID + j0 + (r & 3);
        float f0 = w_hh0[grow * HID + 2 * w];
        float f1 = w_hh0[grow * HID + 2 * w + 1];
        unsigned hi, lo; split2(f0, f1, hi, lo);
        int ws = w ^ ((r & 7) << 2);
        smu[OA0 + r * 256 + ws]        = hi;
        smu[OA0 + 4096 + r * 256 + ws] = lo;
    }
    for (int i = tid; i < 16 * 512; i += NTH) {
        int r = i >> 9, w = i & 511;
        int grow = (r >> 2) * HID + j0 + (r & 3);
        int c0 = 2 * w, c1 = c0 + 1;
        float f0 = (c0 < 512) ? w_ih1[grow*HID + c0] : w_hh1[grow*HID + (c0 - 512)];
        float f1 = (c1 < 512) ? w_ih1[grow*HID + c1] : w_hh1[grow*HID + (c1 - 512)];
        unsigned hi, lo; split2(f0, f1, hi, lo);
        int ws = w ^ ((r & 7) << 2);
        smu[OA1 + r * 512 + ws]        = hi;
        smu[OA1 + 8192 + r * 512 + ws] = lo;
    }
    if (tid < 32) {
        int l = tid >> 4, r = tid & 15;
        int grow = (r >> 2) * HID + j0 + (r & 3);
        bias[tid] = l ? (b_ih1[grow] + b_hh1[grow]) : (b_ih0[grow] + b_hh0[grow]);
    }
    for (int i = tid; i < 512; i += NTH)
        sWo[i] = w_out[oc * HID + i];
    if (tid == 0) mbar_init(mbar, 1);
    __syncthreads();
    // both CTAs' mbarriers live before any multicast targets them
    asm volatile("barrier.cluster.arrive.aligned;" ::: "memory");
    asm volatile("barrier.cluster.wait.aligned;"   ::: "memory");

    // ---- roles ----
    const int wid = tid >> 5, lane = tid & 31;
    const int mm = lane >> 3, rr = lane & 7;
    const int ar = rr + ((mm & 1) << 3);          // A ldmatrix row
    const unsigned aoff = (unsigned)((mm >> 1) << 2);
    const int bb = ((mm >> 1) << 3) + rr;         // B ldmatrix row (batch)
    const unsigned boff = (unsigned)((mm & 1) << 2);
    const unsigned xm = (unsigned)(rr << 2);      // swizzle xor
    const int layerA = tid >> 6, uA = (tid >> 4) & 3, bA = tid & 15;
    // y role (warps 4-7): batch for this warp
    const int yb = (bid >> 5) * 4 + (wid - 4);
    const unsigned xb = (unsigned)((yb & 7) << 2);
    float c_reg = 0.0f, h_last = 0.0f;

    for (int n = 0; n <= TT; n++) {
        const int wr = n & 1, rd = wr ^ 1;

        // ---- stage packed h: cooperative TMA multicast (rank's 32KB half) ----
        if (tid == 0) {
            mbar_expect(mbar, 65536u);
            bulk_mc(sbase + (OB + rank * 8192) * 4u,
                    (const void*)&g_hp[rd][rank * 8192], 32768u,
                    mbar, (unsigned short)0x3);
        }

        // ---- prefetch gx0 (L0 act threads) — overlaps TMA in flight ----
        float gx[4] = {0, 0, 0, 0};
        if (tid < 64 && n < TT) {
            const float* gp = &g_gx0[((size_t)n * NBLK + bid) * 256 + uA * 16 + bA];
            #pragma unroll
            for (int g = 0; g < 4; g++) gx[g] = __ldg(gp + g * 64);
        }

        // ---- wait for both slices (64KB total) ----
        mbar_wait(mbar, (unsigned)(n & 1));

        // ---- tensor-core GEMMs (split-bf16, A+B via ldmatrix) ----
        if (wid < 8) {
            if (n < TT) {   // layer 0: K=512, K-split 8, 4 k-tiles each
                float acc0[4] = {0,0,0,0}, acc1[4] = {0,0,0,0};
                const unsigned w0 = (unsigned)(wid * 32);
                #pragma unroll
                for (int i = 0; i < 4; i++) {
                    const unsigned w = w0 + i * 8;
                    unsigned aw = sbase + (OA0 + ar * 256 + ((w + aoff) ^ xm)) * 4u;
                    unsigned bw = sbase + (OB  + bb * 256 + ((w + boff) ^ xm)) * 4u;
                    unsigned ah[4], al[4], b0,b1,b2,b3, l0,l1,l2,l3;
                    ldsm4(ah[0], ah[1], ah[2], ah[3], aw);
                    ldsm4(al[0], al[1], al[2], al[3], aw + 4096 * 4u);
                    ldsm4(b0, b1, b2, b3, bw);
                    ldsm4(l0, l1, l2, l3, bw + 8192 * 4u);
                    unsigned bh0[2] = {b0, b1}, bh1[2] = {b2, b3};
                    unsigned bl0[2] = {l0, l1}, bl1[2] = {l2, l3};
                    mma_bf16(acc0, ah, bh0);
                    mma_bf16(acc0, ah, bl0);
                    mma_bf16(acc0, al, bh0);
                    mma_bf16(acc1, ah, bh1);
                    mma_bf16(acc1, ah, bl1);
                    mma_bf16(acc1, al, bh1);
                }
                const int base = wid * 256, row = lane >> 2, col = (lane & 3) * 2;
                *(float2*)&red[base +  row      * 16 + col    ] = make_float2(acc0[0], acc0[1]);
                *(float2*)&red[base + (row + 8) * 16 + col    ] = make_float2(acc0[2], acc0[3]);
                *(float2*)&red[base +  row      * 16 + col + 8] = make_float2(acc1[0], acc1[1]);
                *(float2*)&red[base + (row + 8) * 16 + col + 8] = make_float2(acc1[2], acc1[3]);
            }
        } else {
            if (n >= 1) {   // layer 1: K=1024, K-split 8, 8 k-tiles each
                float acc0[4] = {0,0,0,0}, acc1[4] = {0,0,0,0};
                const unsigned wA0 = (unsigned)((wid - 8) * 64);
                const unsigned Lb  = (wid >= 12) ? 4096u : 0u;
                const unsigned wB0 = (wid >= 12) ? wA0 - 256u : wA0;
                #pragma unroll
                for (int i = 0; i < 8; i++) {
                    const unsigned wA = wA0 + i * 8, wB = wB0 + i * 8;
                    unsigned aw = sbase + (OA1 + ar * 512 + ((wA + aoff) ^ xm)) * 4u;
                    unsigned bw = sbase + (OB + Lb + bb * 256 + ((wB + boff) ^ xm)) * 4u;
                    unsigned ah[4], al[4], b0,b1,b2,b3, l0,l1,l2,l3;
                    ldsm4(ah[0], ah[1], ah[2], ah[3], aw);
                    ldsm4(al[0], al[1], al[2], al[3], aw + 8192 * 4u);
                    ldsm4(b0, b1, b2, b3, bw);
                    ldsm4(l0, l1, l2, l3, bw + 8192 * 4u);
                    unsigned bh0[2] = {b0, b1}, bh1[2] = {b2, b3};
                    unsigned bl0[2] = {l0, l1}, bl1[2] = {l2, l3};
                    mma_bf16(acc0, ah, bh0);
                    mma_bf16(acc0, ah, bl0);
                    mma_bf16(acc0, al, bh0);
                    mma_bf16(acc1, ah, bh1);
                    mma_bf16(acc1, ah, bl1);
                    mma_bf16(acc1, al, bh1);
                }
                const int base = wid * 256, row = lane >> 2, col = (lane & 3) * 2;
                *(float2*)&red[base +  row      * 16 + col    ] = make_float2(acc0[0], acc0[1]);
                *(float2*)&red[base + (row + 8) * 16 + col    ] = make_float2(acc0[2], acc0[3]);
                *(float2*)&red[base +  row      * 16 + col + 8] = make_float2(acc1[0], acc1[1]);
                *(float2*)&red[base + (row + 8) * 16 + col + 8] = make_float2(acc1[2], acc1[3]);
            }
        }
        __syncthreads();

        // ---- act warps (0-3): reduce + activations + state update + publish
        //      y warps (4-7): compute y(n-2) from staged hB (runs concurrently)
        if (tid < 128) {
            const bool active = layerA ? (n >= 1) : (n < TT);
            if (active) {
                float g4[4];
                const int rb = layerA * 2048;
                #pragma unroll
                for (int g = 0; g < 4; g++) {
                    const int row = g * 4 + uA;
                    const float* rp = &red[rb + row * 16 + bA];
                    float s = rp[0] + rp[256] + rp[512] + rp[768]
                            + rp[1024] + rp[1280] + rp[1536] + rp[1792];
                    g4[g] = s + bias[layerA * 16 + row] + gx[g];
                }
                float iv = sigf(g4[0]), fv = sigf(g4[1]);
                float gg = tanh_fast(g4[2]), ov = sigf(g4[3]);
                c_reg = fv * c_reg + iv * gg;
                h_last = ov * tanh_fast(c_reg);

                float hp = __shfl_xor_sync(0xffffffffu, h_last, 16);
                if ((tid & 16) == 0) {
                    unsigned whi, wlo; split2(h_last, hp, whi, wlo);
                    const int w  = bid * 2 + (uA >> 1);
                    const int ws = w ^ ((bA & 7) << 2);
                    g_hp[wr][layerA * 4096 + bA * 256 + ws]        = whi;
                    g_hp[wr][8192 + layerA * 4096 + bA * 256 + ws] = wlo;
                }
            }
            asm volatile("fence.acq_rel.gpu;" ::: "memory");  // release publishes
        } else if (wid < 8 && n >= 2) {
            // y[yb][n-2][oc] from staged hB = h1(n-2): h = hi + lo (exact)
            const int t = n - 2;
            float acc = 0.0f;
            #pragma unroll
            for (int i = 0; i < 8; i++) {
                const int w = lane + 32 * i;
                const unsigned idx = (unsigned)(yb * 256) + ((unsigned)w ^ xb);
                unsigned hiw = smu[OB + 4096 + idx];
                unsigned low = smu[OB + 12288 + idx];
                float he = __uint_as_float(hiw << 16) + __uint_as_float(low << 16);
                float ho = __uint_as_float(hiw & 0xFFFF0000u)
                         + __uint_as_float(low & 0xFFFF0000u);
                float2 wv = *(const float2*)&sWo[2 * w];
                acc = fmaf(he, wv.x, acc);
                acc = fmaf(ho, wv.y, acc);
            }
            #pragma unroll
            for (int s = 16; s; s >>= 1)
                acc += __shfl_xor_sync(0xffffffffu, acc, s);
            if (lane == 0)
                out[((size_t)yb * TT + t) * ISZ + oc] = acc + bo;
        }
        grid_barrier((unsigned)(n + 1));
    }

    // ---- epilogue: y(TT-1) from g_hp[0] (published at final iteration) ----
    if (wid >= 4 && wid < 8) {
        float acc = 0.0f;
        #pragma unroll
        for (int i = 0; i < 8; i++) {
            const int w = lane + 32 * i;
            const unsigned idx = (unsigned)(yb * 256) + ((unsigned)w ^ xb);
            unsigned hiw = __ldcg(&g_hp[0][4096 + idx]);
            unsigned low = __ldcg(&g_hp[0][12288 + idx]);
            float he = __uint_as_float(hiw << 16) + __uint_as_float(low << 16);
            float ho = __uint_as_float(hiw & 0xFFFF0000u)
                     + __uint_as_float(low & 0xFFFF0000u);
            float2 wv = *(const float2*)&sWo[2 * w];
            acc = fmaf(he, wv.x, acc);
            acc = fmaf(ho, wv.y, acc);
        }
        #pragma unroll
        for (int s = 16; s; s >>= 1)
            acc += __shfl_xor_sync(0xffffffffu, acc, s);
        if (lane == 0)
            out[((size_t)yb * TT + (TT - 1)) * ISZ + oc] = acc + bo;
    }

    // ---- final h_n, c_n ----
    if (tid < 128) {
        const int j = j0 + uA;
        out[YSZ + (layerA * BT + bA) * HID + j] = h_last;
        out[YSZ + 2*BT*HID + (layerA * BT + bA) * HID + j] = c_reg;
    }

    // no CTA exits while peer multicast could still target its smem
    asm volatile("barrier.cluster.arrive.aligned;" ::: "memory");
    asm volatile("barrier.cluster.wait.aligned;"   ::: "memory");
}

// ----------------------------------------------------------------------------
extern "C" void kernel_launch(void* const* d_in, const int* in_sizes, int n_in,
                              void* d_out, int out_size)
{
    const float* x     = (const float*)d_in[0];
    const float* w_ih0 = (const float*)d_in[1];
    const float* w_hh0 = (const float*)d_in[2];
    const float* b_ih0 = (const float*)d_in[3];
    const float* b_hh0 = (const float*)d_in[4];
    const float* w_ih1 = (const float*)d_in[5];
    const float* w_hh1 = (const float*)d_in[6];
    const float* b_ih1 = (const float*)d_in[7];
    const float* b_hh1 = (const float*)d_in[8];
    const float* w_out = (const float*)d_in[9];
    const float* b_out = (const float*)d_in[10];
    float* out = (float*)d_out;

    cudaFuncSetAttribute(lstm_kernel, cudaFuncAttributeMaxDynamicSharedMemorySize, SMEM_MAIN);

    init_zero_kernel<<<128, 256>>>();
    {
        dim3 g(TT, 8, 1);
        gx0_kernel<<<g, 256>>>(x, w_ih0);
    }
    lstm_kernel<<<NBLK, NTH, SMEM_MAIN>>>(w_hh0, b_ih0, b_hh0,
                                          w_ih1, w_hh1, b_ih1, b_hh1,
                                          w_out, b_out, out);
}

// round 16
// speedup vs baseline: 1.3234x; 1.3234x over previous
#include <cuda_runtime.h>
#include <cuda_bf16.h>

#define HID 512
#define BT  16
#define TT  2048
#define ISZ 32
#define NBLK 128
#define NTH  512
#define YSZ (BT*TT*ISZ)

// ---- shared memory word (u32) layout ---------------------------------------
#define OA0   0                 // L0 A: hi 16x256 | lo 16x256 (w_hh0), swizzled
#define OA1   8192              // L1 A: hi 16x512 | lo 16x512 (w_ih1|w_hh1)
#define OB    24576             // B: hi [L(2)][b(16)][256] | lo same (raw copy of g_hp)
#define ORED  40960             // 16 slabs x 320 floats (batch-major, gates contiguous)
#define OBIAS 46080             // 32 floats
#define OWOUT 46112             // w_out row oc: 512 floats
#define SMEM_MAIN ((OWOUT + 512) * 4)

// ---- device scratch ---------------------------------------------------------
__device__ __align__(16) unsigned g_hp[2][16384];   // packed split-bf16 h (64KB/buf)
__device__ float g_gx0[(size_t)TT*NBLK*256];        // precomputed x@w_ih0^T
__device__ unsigned g_bar_count, g_bar_gen;

// ---- helpers ----------------------------------------------------------------
__device__ __forceinline__ void split2(float f0, float f1, unsigned &hi, unsigned &lo) {
    unsigned h;
    asm("cvt.rn.bf16x2.f32 %0, %1, %2;" : "=r"(h) : "f"(f1), "f"(f0));
    float r0 = f0 - __uint_as_float(h << 16);
    float r1 = f1 - __uint_as_float(h & 0xFFFF0000u);
    unsigned l;
    asm("cvt.rn.bf16x2.f32 %0, %1, %2;" : "=r"(l) : "f"(r1), "f"(r0));
    hi = h; lo = l;
}

__device__ __forceinline__ void mma_bf16(float* c, const unsigned* a, const unsigned* b) {
    asm volatile(
        "mma.sync.aligned.m16n8k16.row.col.f32.bf16.bf16.f32 "
        "{%0,%1,%2,%3}, {%4,%5,%6,%7}, {%8,%9}, {%0,%1,%2,%3};"
        : "+f"(c[0]), "+f"(c[1]), "+f"(c[2]), "+f"(c[3])
        : "r"(a[0]), "r"(a[1]), "r"(a[2]), "r"(a[3]), "r"(b[0]), "r"(b[1]));
}

__device__ __forceinline__ void ldsm4(unsigned &r0, unsigned &r1, unsigned &r2, unsigned &r3,
                                      unsigned addr) {
    asm volatile("ldmatrix.sync.aligned.m8n8.x4.shared.b16 {%0,%1,%2,%3}, [%4];"
                 : "=r"(r0), "=r"(r1), "=r"(r2), "=r"(r3) : "r"(addr));
}

__device__ __forceinline__ float sigf(float v) {
    return __fdividef(1.0f, 1.0f + __expf(-v));
}
__device__ __forceinline__ float tanh_fast(float v) {
    return __fdividef(2.0f, 1.0f + __expf(-2.0f * v)) - 1.0f;
}

// ---- init -------------------------------------------------------------------
__global__ void init_zero_kernel() {
    int i = blockIdx.x * blockDim.x + threadIdx.x;
    if (i < 2 * 16384) (&g_hp[0][0])[i] = 0u;
    if (i == 0) { g_bar_count = 0u; g_bar_gen = 0u; }
}

// gx0[t][blk][g*4+u][b] = dot(x[b,t,:], w_ih0[g*512+blk*4+u, :])
__global__ void gx0_kernel(const float* __restrict__ x, const float* __restrict__ w_ih0) {
    __shared__ float sx[BT][ISZ];
    const int t = blockIdx.x;
    const int tid = threadIdx.x;
    for (int i = tid; i < BT * ISZ; i += 256) {
        int b = i >> 5, k = i & 31;
        sx[b][k] = x[((size_t)b * TT + t) * ISZ + k];
    }
    __syncthreads();
    const int grow = blockIdx.y * 256 + tid;   // 0..2047
    float4 w[8];
    #pragma unroll
    for (int i = 0; i < 8; i++)
        w[i] = *(const float4*)&w_ih0[grow * ISZ + i * 4];
    const int g = grow >> 9, ug = grow & 511;
    const int blk = ug >> 2, u = ug & 3;
    float* outp = &g_gx0[((size_t)t * NBLK + blk) * 256 + (g * 4 + u) * 16];
    #pragma unroll 4
    for (int b = 0; b < BT; b++) {
        float s = 0.0f;
        #pragma unroll
        for (int i = 0; i < 8; i++) {
            s += w[i].x * sx[b][i*4+0] + w[i].y * sx[b][i*4+1]
               + w[i].z * sx[b][i*4+2] + w[i].w * sx[b][i*4+3];
        }
        outp[b] = s;
    }
}

// ---- main persistent kernel (plain launch, no clusters) ---------------------
__global__ void __launch_bounds__(NTH, 1) lstm_kernel(
    const float* __restrict__ w_hh0,
    const float* __restrict__ b_ih0, const float* __restrict__ b_hh0,
    const float* __restrict__ w_ih1, const float* __restrict__ w_hh1,
    const float* __restrict__ b_ih1, const float* __restrict__ b_hh1,
    const float* __restrict__ w_out, const float* __restrict__ b_out,
    float* __restrict__ out)
{
    extern __shared__ unsigned smu[];
    float* red  = reinterpret_cast<float*>(&smu[ORED]);
    float* bias = reinterpret_cast<float*>(&smu[OBIAS]);
    float* sWo  = reinterpret_cast<float*>(&smu[OWOUT]);
    const int tid = threadIdx.x;
    const int bid = blockIdx.x;
    const int j0  = bid * 4;
    const unsigned sbase = (unsigned)__cvta_generic_to_shared(smu);

    // y role: block owns output channel oc for 4 batches
    const int oc = bid & 31;
    const float bo = __ldg(&b_out[oc]);

    // ---- one-time: split-bf16 weights into smem, XOR-swizzled ----
    for (int i = tid; i < 16 * 256; i += NTH) {
        int r = i >> 8, w = i & 255;
        int grow = (r >> 2) * HID + j0 + (r & 3);
        float f0 = w_hh0[grow * HID + 2 * w];
        float f1 = w_hh0[grow * HID + 2 * w + 1];
        unsigned hi, lo; split2(f0, f1, hi, lo);
        int ws = w ^ ((r & 7) << 2);
        smu[OA0 + r * 256 + ws]        = hi;
        smu[OA0 + 4096 + r * 256 + ws] = lo;
    }
    for (int i = tid; i < 16 * 512; i += NTH) {
        int r = i >> 9, w = i & 511;
        int grow = (r >> 2) * HID + j0 + (r & 3);
        int c0 = 2 * w, c1 = c0 + 1;
        float f0 = (c0 < 512) ? w_ih1[grow*HID + c0] : w_hh1[grow*HID + (c0 - 512)];
        float f1 = (c1 < 512) ? w_ih1[grow*HID + c1] : w_hh1[grow*HID + (c1 - 512)];
        unsigned hi, lo; split2(f0, f1, hi, lo);
        int ws = w ^ ((r & 7) << 2);
        smu[OA1 + r * 512 + ws]        = hi;
        smu[OA1 + 8192 + r * 512 + ws] = lo;
    }
    if (tid < 32) {
        int l = tid >> 4, r = tid & 15;
        int grow = (r >> 2) * HID + j0 + (r & 3);
        bias[tid] = l ? (b_ih1[grow] + b_hh1[grow]) : (b_ih0[grow] + b_hh0[grow]);
    }
    for (int i = tid; i < 512; i += NTH)
        sWo[i] = w_out[oc * HID + i];
    __syncthreads();

    // ---- roles ----
    const int wid = tid >> 5, lane = tid & 31;
    const int mm = lane >> 3, rr = lane & 7;
    const int ar = rr + ((mm & 1) << 3);          // A ldmatrix row
    const unsigned aoff = (unsigned)((mm >> 1) << 2);
    const int bb = ((mm >> 1) << 3) + rr;         // B ldmatrix row (batch)
    const unsigned boff = (unsigned)((mm & 1) << 2);
    const unsigned xm = (unsigned)(rr << 2);      // swizzle xor
    const int layerA = tid >> 6, uA = (tid >> 4) & 3, bA = tid & 15;
    // y role (warps 4-7): batch for this warp
    const int yb = (bid >> 5) * 4 + (wid - 4);
    const unsigned xb = (unsigned)((yb & 7) << 2);
    // red writer indices (transposed layout): idx = batch*20 + (row&3)*4 + (row>>2)
    const int pr = (((lane >> 2) & 3) << 2) | (lane >> 4);
    const int b0 = (lane & 3) * 2;
    float c_reg = 0.0f, h_last = 0.0f;

    for (int n = 0; n <= TT; n++) {
        const int wr = n & 1, rd = wr ^ 1;

        // ---- prefetch gx0 (L0 act threads) ----
        float gx[4] = {0, 0, 0, 0};
        if (tid < 64 && n < TT) {
            const float* gp = &g_gx0[((size_t)n * NBLK + bid) * 256 + uA * 16 + bA];
            #pragma unroll
            for (int g = 0; g < 4; g++) gx[g] = __ldg(gp + g * 64);
        }

        // ---- stage packed h (raw linear copy; layout already swizzled) ----
        {
            const uint4* src = (const uint4*)&g_hp[rd][0];
            #pragma unroll
            for (int it = 0; it < 8; it++) {
                int i = tid + it * NTH;            // 0..4095
                *(uint4*)&smu[OB + i * 4] = __ldcg(&src[i]);
            }
        }
        __syncthreads();

        // ---- tensor-core GEMMs (split-bf16, A+B via ldmatrix) ----
        if (wid < 8) {
            if (n < TT) {   // layer 0: K=512, K-split 8, 4 k-tiles each
                float acc0[4] = {0,0,0,0}, acc1[4] = {0,0,0,0};
                const unsigned w0 = (unsigned)(wid * 32);
                #pragma unroll
                for (int i = 0; i < 4; i++) {
                    const unsigned w = w0 + i * 8;
                    unsigned aw = sbase + (OA0 + ar * 256 + ((w + aoff) ^ xm)) * 4u;
                    unsigned bw = sbase + (OB  + bb * 256 + ((w + boff) ^ xm)) * 4u;
                    unsigned ah[4], al[4], b0r,b1r,b2r,b3r, l0,l1,l2,l3;
                    ldsm4(ah[0], ah[1], ah[2], ah[3], aw);
                    ldsm4(al[0], al[1], al[2], al[3], aw + 4096 * 4u);
                    ldsm4(b0r, b1r, b2r, b3r, bw);
                    ldsm4(l0, l1, l2, l3, bw + 8192 * 4u);
                    unsigned bh0[2] = {b0r, b1r}, bh1[2] = {b2r, b3r};
                    unsigned bl0[2] = {l0, l1}, bl1[2] = {l2, l3};
                    mma_bf16(acc0, ah, bh0);
                    mma_bf16(acc0, ah, bl0);
                    mma_bf16(acc0, al, bh0);
                    mma_bf16(acc1, ah, bh1);
                    mma_bf16(acc1, ah, bl1);
                    mma_bf16(acc1, al, bh1);
                }
                const int base = wid * 320;
                red[base + (b0    ) * 20 + pr    ] = acc0[0];
                red[base + (b0 + 1) * 20 + pr    ] = acc0[1];
                red[base + (b0    ) * 20 + pr + 2] = acc0[2];
                red[base + (b0 + 1) * 20 + pr + 2] = acc0[3];
                red[base + (b0 + 8) * 20 + pr    ] = acc1[0];
                red[base + (b0 + 9) * 20 + pr    ] = acc1[1];
                red[base + (b0 + 8) * 20 + pr + 2] = acc1[2];
                red[base + (b0 + 9) * 20 + pr + 2] = acc1[3];
            }
        } else {
            if (n >= 1) {   // layer 1: K=1024, K-split 8, 8 k-tiles each
                float acc0[4] = {0,0,0,0}, acc1[4] = {0,0,0,0};
                const unsigned wA0 = (unsigned)((wid - 8) * 64);
                const unsigned Lb  = (wid >= 12) ? 4096u : 0u;
                const unsigned wB0 = (wid >= 12) ? wA0 - 256u : wA0;
                #pragma unroll
                for (int i = 0; i < 8; i++) {
                    const unsigned wA = wA0 + i * 8, wB = wB0 + i * 8;
                    unsigned aw = sbase + (OA1 + ar * 512 + ((wA + aoff) ^ xm)) * 4u;
                    unsigned bw = sbase + (OB + Lb + bb * 256 + ((wB + boff) ^ xm)) * 4u;
                    unsigned ah[4], al[4], b0r,b1r,b2r,b3r, l0,l1,l2,l3;
                    ldsm4(ah[0], ah[1], ah[2], ah[3], aw);
                    ldsm4(al[0], al[1], al[2], al[3], aw + 8192 * 4u);
                    ldsm4(b0r, b1r, b2r, b3r, bw);
                    ldsm4(l0, l1, l2, l3, bw + 8192 * 4u);
                    unsigned bh0[2] = {b0r, b1r}, bh1[2] = {b2r, b3r};
                    unsigned bl0[2] = {l0, l1}, bl1[2] = {l2, l3};
                    mma_bf16(acc0, ah, bh0);
                    mma_bf16(acc0, ah, bl0);
                    mma_bf16(acc0, al, bh0);
                    mma_bf16(acc1, ah, bh1);
                    mma_bf16(acc1, ah, bl1);
                    mma_bf16(acc1, al, bh1);
                }
                const int base = wid * 320;
                red[base + (b0    ) * 20 + pr    ] = acc0[0];
                red[base + (b0 + 1) * 20 + pr    ] = acc0[1];
                red[base + (b0    ) * 20 + pr + 2] = acc0[2];
                red[base + (b0 + 1) * 20 + pr + 2] = acc0[3];
                red[base + (b0 + 8) * 20 + pr    ] = acc1[0];
                red[base + (b0 + 9) * 20 + pr    ] = acc1[1];
                red[base + (b0 + 8) * 20 + pr + 2] = acc1[2];
                red[base + (b0 + 9) * 20 + pr + 2] = acc1[3];
            }
        }
        __syncthreads();

        // ---- act warps (0-3): float4 reduce + activations + publish
        //      y warps (4-7): compute y(n-2) from staged hB (runs concurrently)
        if (tid < 128) {
            const bool active = layerA ? (n >= 1) : (n < TT);
            if (active) {
                const float* rp = &red[layerA * 8 * 320 + bA * 20 + uA * 4];
                float4 s0 = *(const float4*)&rp[0];
                #pragma unroll
                for (int sl = 1; sl < 8; sl++) {
                    float4 sv = *(const float4*)&rp[sl * 320];
                    s0.x += sv.x; s0.y += sv.y; s0.z += sv.z; s0.w += sv.w;
                }
                float g4[4];
                g4[0] = s0.x + bias[layerA * 16 + 0 * 4 + uA] + gx[0];
                g4[1] = s0.y + bias[layerA * 16 + 1 * 4 + uA] + gx[1];
                g4[2] = s0.z + bias[layerA * 16 + 2 * 4 + uA] + gx[2];
                g4[3] = s0.w + bias[layerA * 16 + 3 * 4 + uA] + gx[3];
                float iv = sigf(g4[0]), fv = sigf(g4[1]);
                float gg = tanh_fast(g4[2]), ov = sigf(g4[3]);
                c_reg = fv * c_reg + iv * gg;
                h_last = ov * tanh_fast(c_reg);

                float hp = __shfl_xor_sync(0xffffffffu, h_last, 16);
                if ((tid & 16) == 0) {
                    unsigned whi, wlo; split2(h_last, hp, whi, wlo);
                    const int w  = bid * 2 + (uA >> 1);
                    const int ws = w ^ ((bA & 7) << 2);
                    g_hp[wr][layerA * 4096 + bA * 256 + ws]        = whi;
                    g_hp[wr][8192 + layerA * 4096 + bA * 256 + ws] = wlo;
                }
            }
            asm volatile("fence.acq_rel.gpu;" ::: "memory");  // release publishes
        } else if (wid < 8 && n >= 2) {
            // y[yb][n-2][oc] from staged hB = h1(n-2): h = hi + lo (exact)
            const int t = n - 2;
            float acc = 0.0f;
            #pragma unroll
            for (int i = 0; i < 8; i++) {
                const int w = lane + 32 * i;
                const unsigned idx = (unsigned)(yb * 256) + ((unsigned)w ^ xb);
                unsigned hiw = smu[OB + 4096 + idx];
                unsigned low = smu[OB + 12288 + idx];
                float he = __uint_as_float(hiw << 16) + __uint_as_float(low << 16);
                float ho = __uint_as_float(hiw & 0xFFFF0000u)
                         + __uint_as_float(low & 0xFFFF0000u);
                float2 wv = *(const float2*)&sWo[2 * w];
                acc = fmaf(he, wv.x, acc);
                acc = fmaf(ho, wv.y, acc);
            }
            #pragma unroll
            for (int s = 16; s; s >>= 1)
                acc += __shfl_xor_sync(0xffffffffu, acc, s);
            if (lane == 0)
                out[((size_t)yb * TT + t) * ISZ + oc] = acc + bo;
        }
        // ---- PROVEN grid barrier (R12/R13) ----
        __syncthreads();
        if (tid == 0) {
            const unsigned target = (unsigned)(n + 1);
            unsigned ticket = atomicAdd(&g_bar_count, 1u);
            if (ticket == target * NBLK - 1u) {
                __threadfence();
                *(volatile unsigned*)&g_bar_gen = target;
            } else {
                volatile unsigned* genp = &g_bar_gen;
                while (*genp < target) { }
            }
            asm volatile("fence.acq_rel.gpu;" ::: "memory");
        }
        __syncthreads();
    }

    // ---- epilogue: y(TT-1) from g_hp[0] (published at final iteration) ----
    if (wid >= 4 && wid < 8) {
        float acc = 0.0f;
        #pragma unroll
        for (int i = 0; i < 8; i++) {
            const int w = lane + 32 * i;
            const unsigned idx = (unsigned)(yb * 256) + ((unsigned)w ^ xb);
            unsigned hiw = __ldcg(&g_hp[0][4096 + idx]);
            unsigned low = __ldcg(&g_hp[0][12288 + idx]);
            float he = __uint_as_float(hiw << 16) + __uint_as_float(low << 16);
            float ho = __uint_as_float(hiw & 0xFFFF0000u)
                     + __uint_as_float(low & 0xFFFF0000u);
            float2 wv = *(const float2*)&sWo[2 * w];
            acc = fmaf(he, wv.x, acc);
            acc = fmaf(ho, wv.y, acc);
        }
        #pragma unroll
        for (int s = 16; s; s >>= 1)
            acc += __shfl_xor_sync(0xffffffffu, acc, s);
        if (lane == 0)
            out[((size_t)yb * TT + (TT - 1)) * ISZ + oc] = acc + bo;
    }

    // ---- final h_n, c_n ----
    if (tid < 128) {
        const int j = j0 + uA;
        out[YSZ + (layerA * BT + bA) * HID + j] = h_last;
        out[YSZ + 2*BT*HID + (layerA * BT + bA) * HID + j] = c_reg;
    }
}

// ----------------------------------------------------------------------------
extern "C" void kernel_launch(void* const* d_in, const int* in_sizes, int n_in,
                              void* d_out, int out_size)
{
    const float* x     = (const float*)d_in[0];
    const float* w_ih0 = (const float*)d_in[1];
    const float* w_hh0 = (const float*)d_in[2];
    const float* b_ih0 = (const float*)d_in[3];
    const float* b_hh0 = (const float*)d_in[4];
    const float* w_ih1 = (const float*)d_in[5];
    const float* w_hh1 = (const float*)d_in[6];
    const float* b_ih1 = (const float*)d_in[7];
    const float* b_hh1 = (const float*)d_in[8];
    const float* w_out = (const float*)d_in[9];
    const float* b_out = (const float*)d_in[10];
    float* out = (float*)d_out;

    cudaFuncSetAttribute(lstm_kernel, cudaFuncAttributeMaxDynamicSharedMemorySize, SMEM_MAIN);

    init_zero_kernel<<<128, 256>>>();
    {
        dim3 g(TT, 8, 1);
        gx0_kernel<<<g, 256>>>(x, w_ih0);
    }
    lstm_kernel<<<NBLK, NTH, SMEM_MAIN>>>(w_hh0, b_ih0, b_hh0,
                                          w_ih1, w_hh1, b_ih1, b_hh1,
                                          w_out, b_out, out);
}

// round 17
// speedup vs baseline: 1.3869x; 1.0480x over previous
#include <cuda_runtime.h>
#include <cuda_bf16.h>

#define HID 512
#define BT  16
#define TT  2048
#define ISZ 32
#define NBLK 128
#define NTH  512
#define YSZ (BT*TT*ISZ)

// ---- shared memory word (u32) layout ---------------------------------------
#define OA0   0                 // L0 A: hi 16x256 | lo 16x256 (w_hh0), swizzled
#define OA1   8192              // L1 A: hi 16x512 | lo 16x512 (w_ih1|w_hh1)
#define OB    24576             // B: hi [L(2)][b(16)][256] | lo same (raw copy of g_hp)
#define ORED  40960             // 16 warps x 256 floats
#define OBIAS 45056             // 32 floats
#define OWOUT 45088             // w_out row oc: 512 floats
#define SMEM_MAIN ((OWOUT + 512) * 4)

// ---- device scratch ---------------------------------------------------------
__device__ __align__(16) unsigned g_hp[2][16384];   // packed split-bf16 h (64KB/buf)
__device__ float g_gx0[(size_t)TT*NBLK*256];        // precomputed x@w_ih0^T
__device__ unsigned g_bar_count, g_bar_gen;

// ---- helpers ----------------------------------------------------------------
__device__ __forceinline__ void split2(float f0, float f1, unsigned &hi, unsigned &lo) {
    unsigned h;
    asm("cvt.rn.bf16x2.f32 %0, %1, %2;" : "=r"(h) : "f"(f1), "f"(f0));
    float r0 = f0 - __uint_as_float(h << 16);
    float r1 = f1 - __uint_as_float(h & 0xFFFF0000u);
    unsigned l;
    asm("cvt.rn.bf16x2.f32 %0, %1, %2;" : "=r"(l) : "f"(r1), "f"(r0));
    hi = h; lo = l;
}

__device__ __forceinline__ void mma_bf16(float* c, const unsigned* a, const unsigned* b) {
    asm volatile(
        "mma.sync.aligned.m16n8k16.row.col.f32.bf16.bf16.f32 "
        "{%0,%1,%2,%3}, {%4,%5,%6,%7}, {%8,%9}, {%0,%1,%2,%3};"
        : "+f"(c[0]), "+f"(c[1]), "+f"(c[2]), "+f"(c[3])
        : "r"(a[0]), "r"(a[1]), "r"(a[2]), "r"(a[3]), "r"(b[0]), "r"(b[1]));
}

__device__ __forceinline__ void ldsm4(unsigned &r0, unsigned &r1, unsigned &r2, unsigned &r3,
                                      unsigned addr) {
    asm volatile("ldmatrix.sync.aligned.m8n8.x4.shared.b16 {%0,%1,%2,%3}, [%4];"
                 : "=r"(r0), "=r"(r1), "=r"(r2), "=r"(r3) : "r"(addr));
}

__device__ __forceinline__ float sigf(float v) {
    return __fdividef(1.0f, 1.0f + __expf(-v));
}
__device__ __forceinline__ float tanh_fast(float v) {
    return __fdividef(2.0f, 1.0f + __expf(-2.0f * v)) - 1.0f;
}

// ---- init -------------------------------------------------------------------
__global__ void init_zero_kernel() {
    int i = blockIdx.x * blockDim.x + threadIdx.x;
    if (i < 2 * 16384) (&g_hp[0][0])[i] = 0u;
    if (i == 0) { g_bar_count = 0u; g_bar_gen = 0u; }
}

// gx0[t][blk][g*4+u][b] = dot(x[b,t,:], w_ih0[g*512+blk*4+u, :])
__global__ void gx0_kernel(const float* __restrict__ x, const float* __restrict__ w_ih0) {
    __shared__ float sx[BT][ISZ];
    const int t = blockIdx.x;
    const int tid = threadIdx.x;
    for (int i = tid; i < BT * ISZ; i += 256) {
        int b = i >> 5, k = i & 31;
        sx[b][k] = x[((size_t)b * TT + t) * ISZ + k];
    }
    __syncthreads();
    const int grow = blockIdx.y * 256 + tid;   // 0..2047
    float4 w[8];
    #pragma unroll
    for (int i = 0; i < 8; i++)
        w[i] = *(const float4*)&w_ih0[grow * ISZ + i * 4];
    const int g = grow >> 9, ug = grow & 511;
    const int blk = ug >> 2, u = ug & 3;
    float* outp = &g_gx0[((size_t)t * NBLK + blk) * 256 + (g * 4 + u) * 16];
    #pragma unroll 4
    for (int b = 0; b < BT; b++) {
        float s = 0.0f;
        #pragma unroll
        for (int i = 0; i < 8; i++) {
            s += w[i].x * sx[b][i*4+0] + w[i].y * sx[b][i*4+1]
               + w[i].z * sx[b][i*4+2] + w[i].w * sx[b][i*4+3];
        }
        outp[b] = s;
    }
}

// ---- main persistent kernel (plain launch, no clusters) ---------------------
__global__ void __launch_bounds__(NTH, 1) lstm_kernel(
    const float* __restrict__ w_hh0,
    const float* __restrict__ b_ih0, const float* __restrict__ b_hh0,
    const float* __restrict__ w_ih1, const float* __restrict__ w_hh1,
    const float* __restrict__ b_ih1, const float* __restrict__ b_hh1,
    const float* __restrict__ w_out, const float* __restrict__ b_out,
    float* __restrict__ out)
{
    extern __shared__ unsigned smu[];
    float* red  = reinterpret_cast<float*>(&smu[ORED]);
    float* bias = reinterpret_cast<float*>(&smu[OBIAS]);
    float* sWo  = reinterpret_cast<float*>(&smu[OWOUT]);
    const int tid = threadIdx.x;
    const int bid = blockIdx.x;
    const int j0  = bid * 4;
    const unsigned sbase = (unsigned)__cvta_generic_to_shared(smu);

    // y role: block owns output channel oc for 4 batches
    const int oc = bid & 31;
    const float bo = __ldg(&b_out[oc]);

    // ---- one-time: split-bf16 weights into smem, XOR-swizzled ----
    for (int i = tid; i < 16 * 256; i += NTH) {
        int r = i >> 8, w = i & 255;
        int grow = (r >> 2) * HID + j0 + (r & 3);
        float f0 = w_hh0[grow * HID + 2 * w];
        float f1 = w_hh0[grow * HID + 2 * w + 1];
        unsigned hi, lo; split2(f0, f1, hi, lo);
        int ws = w ^ ((r & 7) << 2);
        smu[OA0 + r * 256 + ws]        = hi;
        smu[OA0 + 4096 + r * 256 + ws] = lo;
    }
    for (int i = tid; i < 16 * 512; i += NTH) {
        int r = i >> 9, w = i & 511;
        int grow = (r >> 2) * HID + j0 + (r & 3);
        int c0 = 2 * w, c1 = c0 + 1;
        float f0 = (c0 < 512) ? w_ih1[grow*HID + c0] : w_hh1[grow*HID + (c0 - 512)];
        float f1 = (c1 < 512) ? w_ih1[grow*HID + c1] : w_hh1[grow*HID + (c1 - 512)];
        unsigned hi, lo; split2(f0, f1, hi, lo);
        int ws = w ^ ((r & 7) << 2);
        smu[OA1 + r * 512 + ws]        = hi;
        smu[OA1 + 8192 + r * 512 + ws] = lo;
    }
    if (tid < 32) {
        int l = tid >> 4, r = tid & 15;
        int grow = (r >> 2) * HID + j0 + (r & 3);
        bias[tid] = l ? (b_ih1[grow] + b_hh1[grow]) : (b_ih0[grow] + b_hh0[grow]);
    }
    for (int i = tid; i < 512; i += NTH)
        sWo[i] = w_out[oc * HID + i];
    __syncthreads();

    // ---- roles ----
    const int wid = tid >> 5, lane = tid & 31;
    const int mm = lane >> 3, rr = lane & 7;
    const int ar = rr + ((mm & 1) << 3);          // A ldmatrix row
    const unsigned aoff = (unsigned)((mm >> 1) << 2);
    const int bb = ((mm >> 1) << 3) + rr;         // B ldmatrix row (batch)
    const unsigned boff = (unsigned)((mm & 1) << 2);
    const unsigned xm = (unsigned)(rr << 2);      // swizzle xor
    const int layerA = tid >> 6, uA = (tid >> 4) & 3, bA = tid & 15;
    // y role (warps 4-7): batch for this warp
    const int yb = (bid >> 5) * 4 + (wid - 4);
    const unsigned xb = (unsigned)((yb & 7) << 2);
    float c_reg = 0.0f, h_last = 0.0f;

    for (int n = 0; n <= TT; n++) {
        const int wr = n & 1, rd = wr ^ 1;

        // ---- prefetch gx0 (L0 act threads) ----
        float gx[4] = {0, 0, 0, 0};
        if (tid < 64 && n < TT) {
            const float* gp = &g_gx0[((size_t)n * NBLK + bid) * 256 + uA * 16 + bA];
            #pragma unroll
            for (int g = 0; g < 4; g++) gx[g] = __ldg(gp + g * 64);
        }

        // ---- stage packed h (raw linear copy; layout already swizzled) ----
        {
            const uint4* src = (const uint4*)&g_hp[rd][0];
            #pragma unroll
            for (int it = 0; it < 8; it++) {
                int i = tid + it * NTH;            // 0..4095
                *(uint4*)&smu[OB + i * 4] = __ldcg(&src[i]);
            }
        }
        __syncthreads();

        // ---- tensor-core GEMMs (split-bf16, A+B via ldmatrix) ----
        if (wid < 8) {
            if (n < TT) {   // layer 0: K=512, K-split 8, 4 k-tiles each
                float acc0[4] = {0,0,0,0}, acc1[4] = {0,0,0,0};
                const unsigned w0 = (unsigned)(wid * 32);
                #pragma unroll
                for (int i = 0; i < 4; i++) {
                    const unsigned w = w0 + i * 8;
                    unsigned aw = sbase + (OA0 + ar * 256 + ((w + aoff) ^ xm)) * 4u;
                    unsigned bw = sbase + (OB  + bb * 256 + ((w + boff) ^ xm)) * 4u;
                    unsigned ah[4], al[4], b0,b1,b2,b3, l0,l1,l2,l3;
                    ldsm4(ah[0], ah[1], ah[2], ah[3], aw);
                    ldsm4(al[0], al[1], al[2], al[3], aw + 4096 * 4u);
                    ldsm4(b0, b1, b2, b3, bw);
                    ldsm4(l0, l1, l2, l3, bw + 8192 * 4u);
                    unsigned bh0[2] = {b0, b1}, bh1[2] = {b2, b3};
                    unsigned bl0[2] = {l0, l1}, bl1[2] = {l2, l3};
                    mma_bf16(acc0, ah, bh0);
                    mma_bf16(acc0, ah, bl0);
                    mma_bf16(acc0, al, bh0);
                    mma_bf16(acc1, ah, bh1);
                    mma_bf16(acc1, ah, bl1);
                    mma_bf16(acc1, al, bh1);
                }
                const int base = wid * 256, row = lane >> 2, col = (lane & 3) * 2;
                *(float2*)&red[base +  row      * 16 + col    ] = make_float2(acc0[0], acc0[1]);
                *(float2*)&red[base + (row + 8) * 16 + col    ] = make_float2(acc0[2], acc0[3]);
                *(float2*)&red[base +  row      * 16 + col + 8] = make_float2(acc1[0], acc1[1]);
                *(float2*)&red[base + (row + 8) * 16 + col + 8] = make_float2(acc1[2], acc1[3]);
            }
        } else {
            if (n >= 1) {   // layer 1: K=1024, K-split 8, 8 k-tiles each
                float acc0[4] = {0,0,0,0}, acc1[4] = {0,0,0,0};
                const unsigned wA0 = (unsigned)((wid - 8) * 64);
                const unsigned Lb  = (wid >= 12) ? 4096u : 0u;
                const unsigned wB0 = (wid >= 12) ? wA0 - 256u : wA0;
                #pragma unroll
                for (int i = 0; i < 8; i++) {
                    const unsigned wA = wA0 + i * 8, wB = wB0 + i * 8;
                    unsigned aw = sbase + (OA1 + ar * 512 + ((wA + aoff) ^ xm)) * 4u;
                    unsigned bw = sbase + (OB + Lb + bb * 256 + ((wB + boff) ^ xm)) * 4u;
                    unsigned ah[4], al[4], b0,b1,b2,b3, l0,l1,l2,l3;
                    ldsm4(ah[0], ah[1], ah[2], ah[3], aw);
                    ldsm4(al[0], al[1], al[2], al[3], aw + 8192 * 4u);
                    ldsm4(b0, b1, b2, b3, bw);
                    ldsm4(l0, l1, l2, l3, bw + 8192 * 4u);
                    unsigned bh0[2] = {b0, b1}, bh1[2] = {b2, b3};
                    unsigned bl0[2] = {l0, l1}, bl1[2] = {l2, l3};
                    mma_bf16(acc0, ah, bh0);
                    mma_bf16(acc0, ah, bl0);
                    mma_bf16(acc0, al, bh0);
                    mma_bf16(acc1, ah, bh1);
                    mma_bf16(acc1, ah, bl1);
                    mma_bf16(acc1, al, bh1);
                }
                const int base = wid * 256, row = lane >> 2, col = (lane & 3) * 2;
                *(float2*)&red[base +  row      * 16 + col    ] = make_float2(acc0[0], acc0[1]);
                *(float2*)&red[base + (row + 8) * 16 + col    ] = make_float2(acc0[2], acc0[3]);
                *(float2*)&red[base +  row      * 16 + col + 8] = make_float2(acc1[0], acc1[1]);
                *(float2*)&red[base + (row + 8) * 16 + col + 8] = make_float2(acc1[2], acc1[3]);
            }
        }
        __syncthreads();

        // ---- act warps (0-3): reduce + activations + state update + publish
        //      y warps (4-7): compute y(n-2) from staged hB (runs concurrently)
        if (tid < 128) {
            const bool active = layerA ? (n >= 1) : (n < TT);
            if (active) {
                float g4[4];
                const int rb = layerA * 2048;
                #pragma unroll
                for (int g = 0; g < 4; g++) {
                    const int row = g * 4 + uA;
                    const float* rp = &red[rb + row * 16 + bA];
                    float s = rp[0] + rp[256] + rp[512] + rp[768]
                            + rp[1024] + rp[1280] + rp[1536] + rp[1792];
                    g4[g] = s + bias[layerA * 16 + row] + gx[g];
                }
                float iv = sigf(g4[0]), fv = sigf(g4[1]);
                float gg = tanh_fast(g4[2]), ov = sigf(g4[3]);
                c_reg = fv * c_reg + iv * gg;
                h_last = ov * tanh_fast(c_reg);

                float hp = __shfl_xor_sync(0xffffffffu, h_last, 16);
                if ((tid & 16) == 0) {
                    unsigned whi, wlo; split2(h_last, hp, whi, wlo);
                    const int w  = bid * 2 + (uA >> 1);
                    const int ws = w ^ ((bA & 7) << 2);
                    g_hp[wr][layerA * 4096 + bA * 256 + ws]        = whi;
                    g_hp[wr][8192 + layerA * 4096 + bA * 256 + ws] = wlo;
                }
            }
            asm volatile("fence.acq_rel.gpu;" ::: "memory");  // release publishes
        } else if (wid < 8 && n >= 2) {
            // y[yb][n-2][oc] from staged hB = h1(n-2): h = hi + lo (exact)
            const int t = n - 2;
            float acc = 0.0f;
            #pragma unroll
            for (int i = 0; i < 8; i++) {
                const int w = lane + 32 * i;
                const unsigned idx = (unsigned)(yb * 256) + ((unsigned)w ^ xb);
                unsigned hiw = smu[OB + 4096 + idx];
                unsigned low = smu[OB + 12288 + idx];
                float he = __uint_as_float(hiw << 16) + __uint_as_float(low << 16);
                float ho = __uint_as_float(hiw & 0xFFFF0000u)
                         + __uint_as_float(low & 0xFFFF0000u);
                float2 wv = *(const float2*)&sWo[2 * w];
                acc = fmaf(he, wv.x, acc);
                acc = fmaf(ho, wv.y, acc);
            }
            #pragma unroll
            for (int s = 16; s; s >>= 1)
                acc += __shfl_xor_sync(0xffffffffu, acc, s);
            if (lane == 0)
                out[((size_t)yb * TT + t) * ISZ + oc] = acc + bo;
        }
        // ---- PROVEN grid barrier (R12/R13) + backoff in the contended spin ----
        __syncthreads();
        if (tid == 0) {
            const unsigned target = (unsigned)(n + 1);
            unsigned ticket = atomicAdd(&g_bar_count, 1u);
            if (ticket == target * NBLK - 1u) {
                __threadfence();
                *(volatile unsigned*)&g_bar_gen = target;
            } else {
                volatile unsigned* genp = &g_bar_gen;
                while (*genp < target) {
                    asm volatile("nanosleep.u32 32;");  // ease L2 line contention
                }
            }
            asm volatile("fence.acq_rel.gpu;" ::: "memory");
        }
        __syncthreads();
    }

    // ---- epilogue: y(TT-1) from g_hp[0] (published at final iteration) ----
    if (wid >= 4 && wid < 8) {
        float acc = 0.0f;
        #pragma unroll
        for (int i = 0; i < 8; i++) {
            const int w = lane + 32 * i;
            const unsigned idx = (unsigned)(yb * 256) + ((unsigned)w ^ xb);
            unsigned hiw = __ldcg(&g_hp[0][4096 + idx]);
            unsigned low = __ldcg(&g_hp[0][12288 + idx]);
            float he = __uint_as_float(hiw << 16) + __uint_as_float(low << 16);
            float ho = __uint_as_float(hiw & 0xFFFF0000u)
                     + __uint_as_float(low & 0xFFFF0000u);
            float2 wv = *(const float2*)&sWo[2 * w];
            acc = fmaf(he, wv.x, acc);
            acc = fmaf(ho, wv.y, acc);
        }
        #pragma unroll
        for (int s = 16; s; s >>= 1)
            acc += __shfl_xor_sync(0xffffffffu, acc, s);
        if (lane == 0)
            out[((size_t)yb * TT + (TT - 1)) * ISZ + oc] = acc + bo;
    }

    // ---- final h_n, c_n ----
    if (tid < 128) {
        const int j = j0 + uA;
        out[YSZ + (layerA * BT + bA) * HID + j] = h_last;
        out[YSZ + 2*BT*HID + (layerA * BT + bA) * HID + j] = c_reg;
    }
}

// ----------------------------------------------------------------------------
extern "C" void kernel_launch(void* const* d_in, const int* in_sizes, int n_in,
                              void* d_out, int out_size)
{
    const float* x     = (const float*)d_in[0];
    const float* w_ih0 = (const float*)d_in[1];
    const float* w_hh0 = (const float*)d_in[2];
    const float* b_ih0 = (const float*)d_in[3];
    const float* b_hh0 = (const float*)d_in[4];
    const float* w_ih1 = (const float*)d_in[5];
    const float* w_hh1 = (const float*)d_in[6];
    const float* b_ih1 = (const float*)d_in[7];
    const float* b_hh1 = (const float*)d_in[8];
    const float* w_out = (const float*)d_in[9];
    const float* b_out = (const float*)d_in[10];
    float* out = (float*)d_out;

    cudaFuncSetAttribute(lstm_kernel, cudaFuncAttributeMaxDynamicSharedMemorySize, SMEM_MAIN);

    init_zero_kernel<<<128, 256>>>();
    {
        dim3 g(TT, 8, 1);
        gx0_kernel<<<g, 256>>>(x, w_ih0);
    }
    lstm_kernel<<<NBLK, NTH, SMEM_MAIN>>>(w_hh0, b_ih0, b_hh0,
                                          w_ih1, w_hh1, b_ih1, b_hh1,
                                          w_out, b_out, out);
}